// round 12
// baseline (speedup 1.0000x reference)
#include <cuda_runtime.h>
#include <cuda_fp16.h>
#include <cstdint>

#define NN 4000
#define SS 64
#define TT 12
#define K3S 192   // 3*SS
#define NCH 125   // 4000 / 32 n-chunks (k1)
#define KCH 24    // 768 / 32 k-chunks (k2)

// ------------------------- device scratch (no allocs) -------------------------
__device__ __align__(16) float g_h[NN * SS];
__device__ __align__(16) float g_aw[NN * K3S];
__device__ __align__(16) __half g_act_hi[(size_t)TT * NN * SS];
__device__ __align__(16) __half g_act_lo[(size_t)TT * NN * SS];
__device__ __align__(16) __half g_eB_hi[(size_t)TT * NCH * NN * 32];
__device__ __align__(16) __half g_eB_lo[(size_t)TT * NCH * NN * 32];
__device__ __align__(16) __half g_hB_hi[NCH * SS * 32];
__device__ __align__(16) __half g_hB_lo[NCH * SS * 32];
__device__ __align__(16) __half g_WT_hi[K3S * TT * SS];
__device__ __align__(16) __half g_WT_lo[K3S * TT * SS];

// ------------------------- helpers -------------------------
__device__ __forceinline__ uint32_t smem_u32(const void* p) {
    uint32_t a;
    asm("{ .reg .u64 t; cvta.to.shared.u64 t, %1; cvt.u32.u64 %0, t; }" : "=r"(a) : "l"(p));
    return a;
}
__device__ __forceinline__ void cp16(uint32_t dst, const void* src, int bytes) {
    asm volatile("cp.async.cg.shared.global [%0], [%1], 16, %2;" :: "r"(dst), "l"(src), "r"(bytes));
}
__device__ __forceinline__ void cp_commit() { asm volatile("cp.async.commit_group;"); }
__device__ __forceinline__ void cp_wait2()  { asm volatile("cp.async.wait_group 2;"); }
__device__ __forceinline__ void cp_wait1()  { asm volatile("cp.async.wait_group 1;"); }
__device__ __forceinline__ void cp_wait0()  { asm volatile("cp.async.wait_group 0;"); }

__device__ __forceinline__ void ldsm4(uint32_t& r0, uint32_t& r1, uint32_t& r2, uint32_t& r3,
                                      uint32_t addr) {
    asm volatile("ldmatrix.sync.aligned.m8n8.x4.shared.b16 {%0,%1,%2,%3}, [%4];"
                 : "=r"(r0), "=r"(r1), "=r"(r2), "=r"(r3) : "r"(addr));
}
__device__ __forceinline__ void mma16816(float* c, const uint32_t* a, const uint32_t* b) {
    asm volatile("mma.sync.aligned.m16n8k16.row.col.f32.f16.f16.f32 "
                 "{%0,%1,%2,%3}, {%4,%5,%6,%7}, {%8,%9}, {%0,%1,%2,%3};"
                 : "+f"(c[0]), "+f"(c[1]), "+f"(c[2]), "+f"(c[3])
                 : "r"(a[0]), "r"(a[1]), "r"(a[2]), "r"(a[3]), "r"(b[0]), "r"(b[1]));
}
__device__ __forceinline__ uint32_t sw64(int r, uint32_t c) {
    return (uint32_t)(r * 64) + (c ^ (uint32_t)((r & 6) << 3));
}
__device__ __forceinline__ uint32_t pack_h2(float a, float b) {
    __half2 h = __floats2half2_rn(a, b);
    return *(uint32_t*)&h;
}

#define K1_STAGE 24576   // k1: A 8K+8K | B 4K+4K
#define K2_STAGE 16384   // k2: A 4K+4K | B 4K+4K

// =====================================================================
// setup: transpose + hi/lo fp16 split of E -> blocked eB [t][ci][m][32]
// =====================================================================
__global__ void __launch_bounds__(256) esplit(const float* __restrict__ e) {
    __shared__ float tile[32][33];
    const int t = blockIdx.z;
    const int m0 = blockIdx.x * 32;
    const int n0 = blockIdx.y * 32;
    const int ci = n0 >> 5;
    const int tx = threadIdx.x & 31;
    const int ty = threadIdx.x >> 5;
    const float* eb = e + (size_t)t * NN * NN;
#pragma unroll
    for (int i = 0; i < 4; i++) {
        const int n = n0 + ty + i * 8;
        tile[ty + i * 8][tx] = eb[(size_t)n * NN + m0 + tx];
    }
    __syncthreads();
    const size_t rowbase = ((size_t)t * NCH + ci) * NN;
    const int px = threadIdx.x & 15;
    const int py = threadIdx.x >> 4;
#pragma unroll
    for (int i = 0; i < 2; i++) {
        const int ml = py + 16 * i;
        const int m = m0 + ml;
        const float v0 = tile[2 * px][ml];
        const float v1 = tile[2 * px + 1][ml];
        const float h0 = __half2float(__float2half_rn(v0));
        const float h1 = __half2float(__float2half_rn(v1));
        const size_t o = (rowbase + m) * 32 + 2 * px;
        *(uint32_t*)&g_eB_hi[o] = pack_h2(v0, v1);
        *(uint32_t*)&g_eB_lo[o] = pack_h2(v0 - h0, v1 - h1);
    }
}

// one-time: W^T split  WT[n][k] = W[k/64][k%64][n]
__global__ void __launch_bounds__(256) wsplit(const float* __restrict__ W) {
    const int idx = blockIdx.x * 256 + threadIdx.x;
    if (idx >= K3S * TT * SS) return;
    const int n = idx / (TT * SS);
    const int k = idx - n * (TT * SS);
    const float v = W[(size_t)k * K3S + n];
    const __half hi = __float2half_rn(v);
    g_WT_hi[idx] = hi;
    g_WT_lo[idx] = __float2half_rn(v - __half2float(hi));
}

// once before loop: transpose + split h -> blocked hB [ci][s][32]
__global__ void __launch_bounds__(256) hsplit(const int* __restrict__ iters, int it_idx) {
    if (it_idx >= *iters) return;
    __shared__ float tile[32][33];
    const int n0 = blockIdx.x * 32;
    const int ci = n0 >> 5;
    const int s0 = blockIdx.y * 32;
    const int tx = threadIdx.x & 31;
    const int ty = threadIdx.x >> 5;
#pragma unroll
    for (int i = 0; i < 4; i++) {
        const int n = n0 + ty + i * 8;
        tile[ty + i * 8][tx] = g_h[(size_t)n * SS + s0 + tx];
    }
    __syncthreads();
#pragma unroll
    for (int i = 0; i < 4; i++) {
        const int s = s0 + ty + i * 8;
        const float v = tile[tx][ty + i * 8];
        const __half hi = __float2half_rn(v);
        g_hB_hi[((size_t)ci * SS + s) * 32 + tx] = hi;
        g_hB_lo[((size_t)ci * SS + s) * 32 + tx] = __float2half_rn(v - __half2float(hi));
    }
}

// =====================================================================
// K1 (HMMA): act[t,m,s] = sum_n e[t,n,m] * h[n,s] + ba[t,s]  -> fp16 hi/lo
// grid (32 m-tiles, 12 t), block 256. 4-stage x 24KB, wait<=2.
// =====================================================================
__device__ __forceinline__ void k1_load_chunk(int tid, int t, int m0, int ci, uint32_t smem) {
    const uint32_t base = smem + (uint32_t)(ci & 3) * K1_STAGE;
    const size_t arow = ((size_t)t * NCH + ci) * NN;
#pragma unroll
    for (int q = 0; q < 2; q++) {
        const int idx = tid + 256 * q;
        const int r = idx >> 2, c16 = idx & 3;
        const int m = m0 + r;
        const int ok = (m < NN) ? 16 : 0;
        const int mc = (m < NN) ? m : (NN - 1);
        const uint32_t sw = sw64(r, (uint32_t)(c16 * 16));
        const size_t off = (arow + mc) * 32 + c16 * 8;
        cp16(base + sw,        g_eB_hi + off, ok);
        cp16(base + 8192 + sw, g_eB_lo + off, ok);
    }
    {
        const int r = tid >> 2, c16 = tid & 3;
        const uint32_t sw = sw64(r, (uint32_t)(c16 * 16));
        const size_t off = ((size_t)ci * SS + r) * 32 + c16 * 8;
        cp16(base + 16384 + sw, g_hB_hi + off, 16);
        cp16(base + 20480 + sw, g_hB_lo + off, 16);
    }
    cp_commit();
}

__global__ void __launch_bounds__(256) k1_hmma(const float* __restrict__ ba,
                                               const int* __restrict__ iters, int it_idx) {
    if (it_idx >= *iters) return;
    extern __shared__ char dsm[];
    const int tid = threadIdx.x;
    const int wid = tid >> 5;
    const int lid = tid & 31;
    const int tt = blockIdx.y;
    const int m0 = blockIdx.x * 128;
    const uint32_t smem = smem_u32(dsm);

    const int wm = wid & 3;
    const int ws = wid >> 2;

    float acc[2][4][4];
#pragma unroll
    for (int a = 0; a < 2; a++)
#pragma unroll
        for (int b = 0; b < 4; b++)
#pragma unroll
            for (int j = 0; j < 4; j++) acc[a][b][j] = 0.f;

    const int arow = wm * 32 + (lid & 15);
    const uint32_t abyt = (uint32_t)((lid >> 4) << 4);
    const int brow0 = ws * 32 + ((lid >> 4) << 3) + (lid & 7);
    const uint32_t bbyt = (uint32_t)(((lid >> 3) & 1) << 4);

    k1_load_chunk(tid, tt, m0, 0, smem);
    k1_load_chunk(tid, tt, m0, 1, smem);
    k1_load_chunk(tid, tt, m0, 2, smem);

    for (int ci = 0; ci < NCH; ci++) {
        if (ci + 2 < NCH) cp_wait2();
        else if (ci + 1 < NCH) cp_wait1();
        else cp_wait0();
        __syncthreads();

        const uint32_t base = smem + (uint32_t)(ci & 3) * K1_STAGE;
#pragma unroll
        for (int kk = 0; kk < 2; kk++) {
            const uint32_t kb = (uint32_t)(kk * 32);
            uint32_t ah[2][4], al[2][4], bh[2][4], bl[2][4];
#pragma unroll
            for (int a = 0; a < 2; a++) {
                const int r = arow + a * 16;
                const uint32_t ad = base + (uint32_t)(r * 64) + ((kb + abyt) ^ (uint32_t)((r & 6) << 3));
                ldsm4(ah[a][0], ah[a][1], ah[a][2], ah[a][3], ad);
                ldsm4(al[a][0], al[a][1], al[a][2], al[a][3], ad + 8192);
            }
#pragma unroll
            for (int bp = 0; bp < 2; bp++) {
                const int r = brow0 + bp * 16;
                const uint32_t bd = base + 16384 + (uint32_t)(r * 64) + ((kb + bbyt) ^ (uint32_t)((r & 6) << 3));
                ldsm4(bh[bp][0], bh[bp][1], bh[bp][2], bh[bp][3], bd);
                ldsm4(bl[bp][0], bl[bp][1], bl[bp][2], bl[bp][3], bd + 4096);
            }
#pragma unroll
            for (int a = 0; a < 2; a++)
#pragma unroll
                for (int b = 0; b < 4; b++) {
                    uint32_t bfh[2] = { bh[b >> 1][(b & 1) * 2], bh[b >> 1][(b & 1) * 2 + 1] };
                    uint32_t bfl[2] = { bl[b >> 1][(b & 1) * 2], bl[b >> 1][(b & 1) * 2 + 1] };
                    mma16816(acc[a][b], ah[a], bfh);
                    mma16816(acc[a][b], al[a], bfh);
                    mma16816(acc[a][b], ah[a], bfl);
                }
        }
        if (ci + 3 < NCH) k1_load_chunk(tid, tt, m0, ci + 3, smem);
    }

#pragma unroll
    for (int b = 0; b < 4; b++) {
        const int scol = ws * 32 + b * 8 + (lid & 3) * 2;
        const float2 bav = *(const float2*)(ba + tt * SS + scol);
#pragma unroll
        for (int a = 0; a < 2; a++) {
            const int mrow = m0 + wm * 32 + a * 16 + (lid >> 2);
#pragma unroll
            for (int half8 = 0; half8 < 2; half8++) {
                const int mr = mrow + half8 * 8;
                if (mr < NN) {
                    const float ox = acc[a][b][half8 * 2 + 0] + bav.x;
                    const float oy = acc[a][b][half8 * 2 + 1] + bav.y;
                    const float hx = __half2float(__float2half_rn(ox));
                    const float hy = __half2float(__float2half_rn(oy));
                    const size_t o = ((size_t)tt * NN + mr) * SS + scol;
                    *(uint32_t*)&g_act_hi[o] = pack_h2(ox, oy);
                    *(uint32_t*)&g_act_lo[o] = pack_h2(ox - hx, oy - hy);
                }
            }
        }
    }
}

// =====================================================================
// K2 (HMMA): aw[m,n] = sum_k act2[m][k] * WT[n][k] + 12*bw[n]
// m-tile 64, n-tile 64 -> grid (63, 3) = 189 CTAs. 4-stage x 16KB.
// 8 warps: wm = wid&1 (m32), wn = wid>>1 (n16).
// =====================================================================
__device__ __forceinline__ void k2_load_chunk(int tid, int n0, int m0, int ci, uint32_t smem) {
    const uint32_t base = smem + (uint32_t)(ci & 3) * K2_STAGE;
    const int t = ci >> 1;
    const int sh = (ci & 1) * 32;
    {   // A: 64 rows(m) x 32 k
        const int r = tid >> 2, c16 = tid & 3;
        const int m = m0 + r;
        const int ok = (m < NN) ? 16 : 0;
        const int mc = (m < NN) ? m : (NN - 1);
        const uint32_t sw = sw64(r, (uint32_t)(c16 * 16));
        const size_t off = ((size_t)t * NN + mc) * SS + sh + c16 * 8;
        cp16(base + sw,        g_act_hi + off, ok);
        cp16(base + 4096 + sw, g_act_lo + off, ok);
    }
    {   // B: 64 rows(n) x 32 k
        const int r = tid >> 2, c16 = tid & 3;
        const uint32_t sw = sw64(r, (uint32_t)(c16 * 16));
        const size_t off = (size_t)(n0 + r) * (TT * SS) + t * SS + sh + c16 * 8;
        cp16(base + 8192 + sw,  g_WT_hi + off, 16);
        cp16(base + 12288 + sw, g_WT_lo + off, 16);
    }
    cp_commit();
}

__global__ void __launch_bounds__(256) k2_hmma(const float* __restrict__ bw,
                                               const int* __restrict__ iters, int it_idx) {
    if (it_idx >= *iters) return;
    extern __shared__ char dsm[];
    const int tid = threadIdx.x;
    const int wid = tid >> 5;
    const int lid = tid & 31;
    const int n0 = blockIdx.y * 64;
    const int m0 = blockIdx.x * 64;
    const uint32_t smem = smem_u32(dsm);

    const int wm = wid & 1;
    const int wn = wid >> 1;

    float acc[2][2][4];
#pragma unroll
    for (int a = 0; a < 2; a++)
#pragma unroll
        for (int b = 0; b < 2; b++)
#pragma unroll
            for (int j = 0; j < 4; j++) acc[a][b][j] = 0.f;

    const int arow = wm * 32 + (lid & 15);
    const uint32_t abyt = (uint32_t)((lid >> 4) << 4);
    const int brow0 = wn * 16 + ((lid >> 4) << 3) + (lid & 7);
    const uint32_t bbyt = (uint32_t)(((lid >> 3) & 1) << 4);

    k2_load_chunk(tid, n0, m0, 0, smem);
    k2_load_chunk(tid, n0, m0, 1, smem);
    k2_load_chunk(tid, n0, m0, 2, smem);

    for (int ci = 0; ci < KCH; ci++) {
        if (ci + 2 < KCH) cp_wait2();
        else if (ci + 1 < KCH) cp_wait1();
        else cp_wait0();
        __syncthreads();

        const uint32_t base = smem + (uint32_t)(ci & 3) * K2_STAGE;
#pragma unroll
        for (int kk = 0; kk < 2; kk++) {
            const uint32_t kb = (uint32_t)(kk * 32);
            uint32_t ah[2][4], al[2][4], bh[4], bl[4];
#pragma unroll
            for (int a = 0; a < 2; a++) {
                const int r = arow + a * 16;
                const uint32_t ad = base + (uint32_t)(r * 64) + ((kb + abyt) ^ (uint32_t)((r & 6) << 3));
                ldsm4(ah[a][0], ah[a][1], ah[a][2], ah[a][3], ad);
                ldsm4(al[a][0], al[a][1], al[a][2], al[a][3], ad + 4096);
            }
            {
                const int r = brow0;
                const uint32_t bd = base + 8192 + (uint32_t)(r * 64) + ((kb + bbyt) ^ (uint32_t)((r & 6) << 3));
                ldsm4(bh[0], bh[1], bh[2], bh[3], bd);
                ldsm4(bl[0], bl[1], bl[2], bl[3], bd + 4096);
            }
#pragma unroll
            for (int a = 0; a < 2; a++)
#pragma unroll
                for (int b = 0; b < 2; b++) {
                    uint32_t bfh[2] = { bh[b * 2], bh[b * 2 + 1] };
                    uint32_t bfl[2] = { bl[b * 2], bl[b * 2 + 1] };
                    mma16816(acc[a][b], ah[a], bfh);
                    mma16816(acc[a][b], al[a], bfh);
                    mma16816(acc[a][b], ah[a], bfl);
                }
        }
        if (ci + 3 < KCH) k2_load_chunk(tid, n0, m0, ci + 3, smem);
    }

#pragma unroll
    for (int b = 0; b < 2; b++) {
        const int ncol = n0 + wn * 16 + b * 8 + (lid & 3) * 2;
        const float2 bwv = *(const float2*)(bw + ncol);
#pragma unroll
        for (int a = 0; a < 2; a++) {
            const int mrow = m0 + wm * 32 + a * 16 + (lid >> 2);
            if (mrow < NN) {
                float2 o = { acc[a][b][0] + 12.0f * bwv.x, acc[a][b][1] + 12.0f * bwv.y };
                *(float2*)&g_aw[(size_t)mrow * K3S + ncol] = o;
            }
            if (mrow + 8 < NN) {
                float2 o = { acc[a][b][2] + 12.0f * bwv.x, acc[a][b][3] + 12.0f * bwv.y };
                *(float2*)&g_aw[(size_t)(mrow + 8) * K3S + ncol] = o;
            }
        }
    }
}

// =====================================================================
// K34 (fused GRU update + hB production): 32 rows/block, grid 125.
// Writes g_h AND transposed/split g_hB for the next iteration's k1.
// =====================================================================
#define SHH_PITCH 65
#define K34_FLOATS (64*128 + 64*64 + 32*SHH_PITCH + 32*64 + 32*64)
#define K34_SMEM (K34_FLOATS * 4)

__global__ void __launch_bounds__(256) k34_update(const float* __restrict__ uz_ur,
                                                  const float* __restrict__ uh,
                                                  const int* __restrict__ iters,
                                                  int it_idx) {
    if (it_idx >= *iters) return;
    extern __shared__ float sm[];
    float* sUZ = sm;                         // [64][128]
    float* sUH = sUZ + 64 * 128;             // [64][64]
    float* shh = sUH + 64 * 64;              // [32][65] pitched
    float* srh = shh + 32 * SHH_PITCH;       // [32][64]
    float* sz  = srh + 32 * 64;              // [32][64]

    const int ci = blockIdx.x;               // n-chunk == m-chunk of 32
    const int m0 = ci * 32;
    const int tid = threadIdx.x;

#pragma unroll
    for (int i = 0; i < 8; i++)
        ((float4*)sUZ)[tid + 256 * i] = ((const float4*)uz_ur)[tid + 256 * i];
#pragma unroll
    for (int i = 0; i < 4; i++)
        ((float4*)sUH)[tid + 256 * i] = ((const float4*)uh)[tid + 256 * i];
#pragma unroll
    for (int j = 0; j < 8; j++) {            // pitched copy of h rows m0..m0+31
        const int idx = tid + 256 * j;
        const int r = idx >> 6, s = idx & 63;
        shh[r * SHH_PITCH + s] = g_h[(size_t)(m0 + r) * SS + s];
    }
    __syncthreads();

    const int tx = tid & 15, ty = tid >> 4;
    {   // gates: 2 rows per thread, 8 k each
        const int k0 = tx * 8;
#pragma unroll
        for (int rr = 0; rr < 2; rr++) {
            const int r = ty + rr * 16;
            const int m = m0 + r;
            float accv[8] = {0.f, 0.f, 0.f, 0.f, 0.f, 0.f, 0.f, 0.f};
#pragma unroll 8
            for (int s = 0; s < 64; s++) {
                const float hv = shh[r * SHH_PITCH + s];
#pragma unroll
                for (int j = 0; j < 8; j++) accv[j] += hv * sUZ[s * 128 + k0 + j];
            }
#pragma unroll
            for (int j = 0; j < 8; j++) {
                const int k = k0 + j;
                const float gt = g_aw[(size_t)m * K3S + k] + accv[j];
                const float sg = 1.0f / (1.0f + __expf(-gt));
                if (k < 64) sz[r * 64 + k] = sg;
                else        srh[r * 64 + (k - 64)] = sg * shh[r * SHH_PITCH + (k - 64)];
            }
        }
    }
    __syncthreads();
    {   // candidate + update: 2 rows per thread, 4 k each; write h + shh
        const int k0 = tx * 4;
#pragma unroll
        for (int rr = 0; rr < 2; rr++) {
            const int r = ty + rr * 16;
            const int m = m0 + r;
            float accv[4] = {0.f, 0.f, 0.f, 0.f};
#pragma unroll 8
            for (int s = 0; s < 64; s++) {
                const float rv = srh[r * 64 + s];
#pragma unroll
                for (int j = 0; j < 4; j++) accv[j] += rv * sUH[s * 64 + k0 + j];
            }
#pragma unroll
            for (int j = 0; j < 4; j++) {
                const int k = k0 + j;
                const float hhv = tanhf(g_aw[(size_t)m * K3S + 128 + k] + accv[j]);
                const float zv = sz[r * 64 + k];
                const float hv = shh[r * SHH_PITCH + k];
                const float hnew = (1.0f - zv) * hv + zv * hhv;
                g_h[(size_t)m * SS + k] = hnew;
                shh[r * SHH_PITCH + k] = hnew;
            }
        }
    }
    __syncthreads();
    {   // hB transpose-write: [ci][s][n'=m-m0] hi/lo, u32 (2 n') per store
        const int pr = tid & 15;             // n-pair: n' = 2pr, 2pr+1
        const int sb = tid >> 4;             // s base (16 s, step 16)
#pragma unroll
        for (int j = 0; j < 4; j++) {
            const int s = sb + 16 * j;
            const float v0 = shh[(2 * pr) * SHH_PITCH + s];
            const float v1 = shh[(2 * pr + 1) * SHH_PITCH + s];
            const float h0 = __half2float(__float2half_rn(v0));
            const float h1 = __half2float(__float2half_rn(v1));
            const size_t o = ((size_t)ci * SS + s) * 32 + 2 * pr;
            *(uint32_t*)&g_hB_hi[o] = pack_h2(v0, v1);
            *(uint32_t*)&g_hB_lo[o] = pack_h2(v0 - h0, v1 - h1);
        }
    }
}

// ---- copies ----
__global__ void kcopy_in(const float* __restrict__ x) {
    const int i = blockIdx.x * 256 + threadIdx.x;
    if (i < NN * SS) g_h[i] = x[i];
}
__global__ void kcopy_out(float* __restrict__ out) {
    const int i = blockIdx.x * 256 + threadIdx.x;
    if (i < NN * SS) out[i] = g_h[i];
}

extern "C" void kernel_launch(void* const* d_in, const int* in_sizes, int n_in,
                              void* d_out, int out_size) {
    const float* x     = (const float*)d_in[0];
    const float* e     = (const float*)d_in[1];
    const float* ba    = (const float*)d_in[2];
    const float* bw    = (const float*)d_in[3];
    const float* W     = (const float*)d_in[4];
    const float* uz_ur = (const float*)d_in[5];
    const float* uh    = (const float*)d_in[6];
    const int*   iters = (const int*)d_in[7];
    float* out = (float*)d_out;

    cudaFuncSetAttribute(k1_hmma, cudaFuncAttributeMaxDynamicSharedMemorySize, 4 * K1_STAGE);
    cudaFuncSetAttribute(k1_hmma, cudaFuncAttributePreferredSharedMemoryCarveout, 100);
    cudaFuncSetAttribute(k2_hmma, cudaFuncAttributeMaxDynamicSharedMemorySize, 4 * K2_STAGE);
    cudaFuncSetAttribute(k2_hmma, cudaFuncAttributePreferredSharedMemoryCarveout, 100);
    cudaFuncSetAttribute(k34_update, cudaFuncAttributeMaxDynamicSharedMemorySize, K34_SMEM);

    const int cpb = (NN * SS + 255) / 256;
    kcopy_in<<<cpb, 256>>>(x);

    dim3 ge(NN / 32, NN / 32, TT);
    esplit<<<ge, 256>>>(e);
    wsplit<<<(K3S * TT * SS + 255) / 256, 256>>>(W);

    const dim3 gh(NN / 32, SS / 32);
    hsplit<<<gh, 256>>>(iters, 0);   // hB for iteration 0 only; k34 maintains it after

    const dim3 g1((NN + 127) / 128, TT);
    const dim3 g2((NN + 63) / 64, 3);
    const int g34 = NN / 32;

    for (int it = 0; it < 10; it++) {
        k1_hmma<<<g1, 256, 4 * K1_STAGE>>>(ba, iters, it);
        k2_hmma<<<g2, 256, 4 * K2_STAGE>>>(bw, iters, it);
        k34_update<<<g34, 256, K34_SMEM>>>(uz_ur, uh, iters, it);
    }

    kcopy_out<<<cpb, 256>>>(out);
}

// round 13
// speedup vs baseline: 1.0104x; 1.0104x over previous
#include <cuda_runtime.h>
#include <cuda_fp16.h>
#include <cstdint>

#define NN 4000
#define SS 64
#define TT 12
#define K3S 192   // 3*SS
#define NCH 125   // 4000 / 32 n-chunks (k1)
#define KCH 24    // 768 / 32 k-chunks (k234)

// ------------------------- device scratch (no allocs) -------------------------
__device__ __align__(16) float g_h[NN * SS];
__device__ __align__(16) __half g_act_hi[(size_t)TT * NN * SS];
__device__ __align__(16) __half g_act_lo[(size_t)TT * NN * SS];
__device__ __align__(16) __half g_eB_hi[(size_t)TT * NCH * NN * 32];
__device__ __align__(16) __half g_eB_lo[(size_t)TT * NCH * NN * 32];
__device__ __align__(16) __half g_hB_hi[NCH * SS * 32];
__device__ __align__(16) __half g_hB_lo[NCH * SS * 32];
__device__ __align__(16) __half g_WT_hi[K3S * TT * SS];
__device__ __align__(16) __half g_WT_lo[K3S * TT * SS];

// ------------------------- helpers -------------------------
__device__ __forceinline__ uint32_t smem_u32(const void* p) {
    uint32_t a;
    asm("{ .reg .u64 t; cvta.to.shared.u64 t, %1; cvt.u32.u64 %0, t; }" : "=r"(a) : "l"(p));
    return a;
}
__device__ __forceinline__ void cp16(uint32_t dst, const void* src, int bytes) {
    asm volatile("cp.async.cg.shared.global [%0], [%1], 16, %2;" :: "r"(dst), "l"(src), "r"(bytes));
}
__device__ __forceinline__ void cp_commit() { asm volatile("cp.async.commit_group;"); }
__device__ __forceinline__ void cp_wait2()  { asm volatile("cp.async.wait_group 2;"); }
__device__ __forceinline__ void cp_wait1()  { asm volatile("cp.async.wait_group 1;"); }
__device__ __forceinline__ void cp_wait0()  { asm volatile("cp.async.wait_group 0;"); }

__device__ __forceinline__ void ldsm4(uint32_t& r0, uint32_t& r1, uint32_t& r2, uint32_t& r3,
                                      uint32_t addr) {
    asm volatile("ldmatrix.sync.aligned.m8n8.x4.shared.b16 {%0,%1,%2,%3}, [%4];"
                 : "=r"(r0), "=r"(r1), "=r"(r2), "=r"(r3) : "r"(addr));
}
__device__ __forceinline__ void mma16816(float* c, const uint32_t* a, const uint32_t* b) {
    asm volatile("mma.sync.aligned.m16n8k16.row.col.f32.f16.f16.f32 "
                 "{%0,%1,%2,%3}, {%4,%5,%6,%7}, {%8,%9}, {%0,%1,%2,%3};"
                 : "+f"(c[0]), "+f"(c[1]), "+f"(c[2]), "+f"(c[3])
                 : "r"(a[0]), "r"(a[1]), "r"(a[2]), "r"(a[3]), "r"(b[0]), "r"(b[1]));
}
__device__ __forceinline__ uint32_t sw64(int r, uint32_t c) {
    return (uint32_t)(r * 64) + (c ^ (uint32_t)((r & 6) << 3));
}
__device__ __forceinline__ uint32_t pack_h2(float a, float b) {
    __half2 h = __floats2half2_rn(a, b);
    return *(uint32_t*)&h;
}

#define K1_STAGE 24576   // k1: A 8K+8K | B 4K+4K
#define P2_STAGE 28672   // k234: A 2K+2K | B 12K+12K

// =====================================================================
// setup: contiguous-read transpose + fp16 split of E -> eB [t][ci][m][32]
// block tile: 32 n-rows x 256 m-cols; reads are 1 KB contiguous runs.
// =====================================================================
__global__ void __launch_bounds__(256) esplit(const float* __restrict__ e) {
    __shared__ float tile[256 * 33];   // [m_local][n'] pitch 33
    const int t = blockIdx.z;
    const int ci = blockIdx.y;
    const int n0 = ci * 32;
    const int m0 = blockIdx.x * 256;
    const int tid = threadIdx.x;
    const float* eb = e + (size_t)t * NN * NN;

#pragma unroll
    for (int j = 0; j < 8; j++) {
        const int idx = tid + 256 * j;       // 2048 float4 slots
        const int r = idx >> 6;              // n-row 0..31
        const int c4 = idx & 63;             // float4 col
        const int m = m0 + c4 * 4;
        float4 v = make_float4(0.f, 0.f, 0.f, 0.f);
        if (m < NN) v = *(const float4*)(eb + (size_t)(n0 + r) * NN + m);
        const int ml = c4 * 4;
        tile[(ml + 0) * 33 + r] = v.x;
        tile[(ml + 1) * 33 + r] = v.y;
        tile[(ml + 2) * 33 + r] = v.z;
        tile[(ml + 3) * 33 + r] = v.w;
    }
    __syncthreads();

    const size_t rowbase = ((size_t)t * NCH + ci) * NN;
    const int px = tid & 15;     // n-pair
    const int my = tid >> 4;     // m sub-row
#pragma unroll
    for (int p = 0; p < 16; p++) {
        const int ml = p * 16 + my;
        const int m = m0 + ml;
        if (m < NN) {
            const float v0 = tile[ml * 33 + 2 * px];
            const float v1 = tile[ml * 33 + 2 * px + 1];
            const float h0 = __half2float(__float2half_rn(v0));
            const float h1 = __half2float(__float2half_rn(v1));
            const size_t o = (rowbase + m) * 32 + 2 * px;
            *(uint32_t*)&g_eB_hi[o] = pack_h2(v0, v1);
            *(uint32_t*)&g_eB_lo[o] = pack_h2(v0 - h0, v1 - h1);
        }
    }
}

// one-time: W^T split  WT[n][k] = W[k/64][k%64][n]
__global__ void __launch_bounds__(256) wsplit(const float* __restrict__ W) {
    const int idx = blockIdx.x * 256 + threadIdx.x;
    if (idx >= K3S * TT * SS) return;
    const int n = idx / (TT * SS);
    const int k = idx - n * (TT * SS);
    const float v = W[(size_t)k * K3S + n];
    const __half hi = __float2half_rn(v);
    g_WT_hi[idx] = hi;
    g_WT_lo[idx] = __float2half_rn(v - __half2float(hi));
}

// once before loop: transpose + split h -> blocked hB [ci][s][32]
__global__ void __launch_bounds__(256) hsplit(const int* __restrict__ iters, int it_idx) {
    if (it_idx >= *iters) return;
    __shared__ float tile[32][33];
    const int n0 = blockIdx.x * 32;
    const int ci = n0 >> 5;
    const int s0 = blockIdx.y * 32;
    const int tx = threadIdx.x & 31;
    const int ty = threadIdx.x >> 5;
#pragma unroll
    for (int i = 0; i < 4; i++) {
        const int n = n0 + ty + i * 8;
        tile[ty + i * 8][tx] = g_h[(size_t)n * SS + s0 + tx];
    }
    __syncthreads();
#pragma unroll
    for (int i = 0; i < 4; i++) {
        const int s = s0 + ty + i * 8;
        const float v = tile[tx][ty + i * 8];
        const __half hi = __float2half_rn(v);
        g_hB_hi[((size_t)ci * SS + s) * 32 + tx] = hi;
        g_hB_lo[((size_t)ci * SS + s) * 32 + tx] = __float2half_rn(v - __half2float(hi));
    }
}

// =====================================================================
// K1 (HMMA): act[t,m,s] = sum_n e[t,n,m] * h[n,s] + ba[t,s]  -> fp16 hi/lo
// grid (32 m-tiles, 12 t), block 256. 4-stage x 24KB, wait<=2.  (unchanged)
// =====================================================================
__device__ __forceinline__ void k1_load_chunk(int tid, int t, int m0, int ci, uint32_t smem) {
    const uint32_t base = smem + (uint32_t)(ci & 3) * K1_STAGE;
    const size_t arow = ((size_t)t * NCH + ci) * NN;
#pragma unroll
    for (int q = 0; q < 2; q++) {
        const int idx = tid + 256 * q;
        const int r = idx >> 2, c16 = idx & 3;
        const int m = m0 + r;
        const int ok = (m < NN) ? 16 : 0;
        const int mc = (m < NN) ? m : (NN - 1);
        const uint32_t sw = sw64(r, (uint32_t)(c16 * 16));
        const size_t off = (arow + mc) * 32 + c16 * 8;
        cp16(base + sw,        g_eB_hi + off, ok);
        cp16(base + 8192 + sw, g_eB_lo + off, ok);
    }
    {
        const int r = tid >> 2, c16 = tid & 3;
        const uint32_t sw = sw64(r, (uint32_t)(c16 * 16));
        const size_t off = ((size_t)ci * SS + r) * 32 + c16 * 8;
        cp16(base + 16384 + sw, g_hB_hi + off, 16);
        cp16(base + 20480 + sw, g_hB_lo + off, 16);
    }
    cp_commit();
}

__global__ void __launch_bounds__(256) k1_hmma(const float* __restrict__ ba,
                                               const int* __restrict__ iters, int it_idx) {
    if (it_idx >= *iters) return;
    extern __shared__ char dsm[];
    const int tid = threadIdx.x;
    const int wid = tid >> 5;
    const int lid = tid & 31;
    const int tt = blockIdx.y;
    const int m0 = blockIdx.x * 128;
    const uint32_t smem = smem_u32(dsm);

    const int wm = wid & 3;
    const int ws = wid >> 2;

    float acc[2][4][4];
#pragma unroll
    for (int a = 0; a < 2; a++)
#pragma unroll
        for (int b = 0; b < 4; b++)
#pragma unroll
            for (int j = 0; j < 4; j++) acc[a][b][j] = 0.f;

    const int arow = wm * 32 + (lid & 15);
    const uint32_t abyt = (uint32_t)((lid >> 4) << 4);
    const int brow0 = ws * 32 + ((lid >> 4) << 3) + (lid & 7);
    const uint32_t bbyt = (uint32_t)(((lid >> 3) & 1) << 4);

    k1_load_chunk(tid, tt, m0, 0, smem);
    k1_load_chunk(tid, tt, m0, 1, smem);
    k1_load_chunk(tid, tt, m0, 2, smem);

    for (int ci = 0; ci < NCH; ci++) {
        if (ci + 2 < NCH) cp_wait2();
        else if (ci + 1 < NCH) cp_wait1();
        else cp_wait0();
        __syncthreads();

        const uint32_t base = smem + (uint32_t)(ci & 3) * K1_STAGE;
#pragma unroll
        for (int kk = 0; kk < 2; kk++) {
            const uint32_t kb = (uint32_t)(kk * 32);
            uint32_t ah[2][4], al[2][4], bh[2][4], bl[2][4];
#pragma unroll
            for (int a = 0; a < 2; a++) {
                const int r = arow + a * 16;
                const uint32_t ad = base + (uint32_t)(r * 64) + ((kb + abyt) ^ (uint32_t)((r & 6) << 3));
                ldsm4(ah[a][0], ah[a][1], ah[a][2], ah[a][3], ad);
                ldsm4(al[a][0], al[a][1], al[a][2], al[a][3], ad + 8192);
            }
#pragma unroll
            for (int bp = 0; bp < 2; bp++) {
                const int r = brow0 + bp * 16;
                const uint32_t bd = base + 16384 + (uint32_t)(r * 64) + ((kb + bbyt) ^ (uint32_t)((r & 6) << 3));
                ldsm4(bh[bp][0], bh[bp][1], bh[bp][2], bh[bp][3], bd);
                ldsm4(bl[bp][0], bl[bp][1], bl[bp][2], bl[bp][3], bd + 4096);
            }
#pragma unroll
            for (int a = 0; a < 2; a++)
#pragma unroll
                for (int b = 0; b < 4; b++) {
                    uint32_t bfh[2] = { bh[b >> 1][(b & 1) * 2], bh[b >> 1][(b & 1) * 2 + 1] };
                    uint32_t bfl[2] = { bl[b >> 1][(b & 1) * 2], bl[b >> 1][(b & 1) * 2 + 1] };
                    mma16816(acc[a][b], ah[a], bfh);
                    mma16816(acc[a][b], al[a], bfh);
                    mma16816(acc[a][b], ah[a], bfl);
                }
        }
        if (ci + 3 < NCH) k1_load_chunk(tid, tt, m0, ci + 3, smem);
    }

#pragma unroll
    for (int b = 0; b < 4; b++) {
        const int scol = ws * 32 + b * 8 + (lid & 3) * 2;
        const float2 bav = *(const float2*)(ba + tt * SS + scol);
#pragma unroll
        for (int a = 0; a < 2; a++) {
            const int mrow = m0 + wm * 32 + a * 16 + (lid >> 2);
#pragma unroll
            for (int half8 = 0; half8 < 2; half8++) {
                const int mr = mrow + half8 * 8;
                if (mr < NN) {
                    const float ox = acc[a][b][half8 * 2 + 0] + bav.x;
                    const float oy = acc[a][b][half8 * 2 + 1] + bav.y;
                    const float hx = __half2float(__float2half_rn(ox));
                    const float hy = __half2float(__float2half_rn(oy));
                    const size_t o = ((size_t)tt * NN + mr) * SS + scol;
                    *(uint32_t*)&g_act_hi[o] = pack_h2(ox, oy);
                    *(uint32_t*)&g_act_lo[o] = pack_h2(ox - hx, oy - hy);
                }
            }
        }
    }
}

// =====================================================================
// K234 (fused): per 32-row m-chunk (grid 125, exact):
//   aw[32][192] = act2[m][k] @ WT[n][k]  (HMMA, K=768, aw stays in smem)
//   then GRU gates/candidate/update + hB transpose-write.
// smem: [0,48K) U matrices | [48K, 48K+3*28K) pipeline (reused for GRU).
// =====================================================================
#define P2_U    0
#define P2_PIPE 49152
#define P2_DSM  (49152 + 3 * P2_STAGE)   // 135168

__device__ __forceinline__ void k234_load_chunk(int tid, int m0, int ci, uint32_t smem) {
    const uint32_t base = smem + P2_PIPE + (uint32_t)(ci % 3) * P2_STAGE;
    const int t = ci >> 1;
    const int sh = (ci & 1) * 32;
    if (tid < 128) {   // A: 32 rows(m) x 32 k
        const int r = tid >> 2, c16 = tid & 3;
        const int m = m0 + r;
        const uint32_t sw = sw64(r, (uint32_t)(c16 * 16));
        const size_t off = ((size_t)t * NN + m) * SS + sh + c16 * 8;
        cp16(base + sw,        g_act_hi + off, 16);
        cp16(base + 2048 + sw, g_act_lo + off, 16);
    }
#pragma unroll
    for (int q = 0; q < 3; q++) {   // B: 192 rows(n) x 32 k
        const int idx = tid + 256 * q;
        const int r = idx >> 2, c16 = idx & 3;
        const uint32_t sw = sw64(r, (uint32_t)(c16 * 16));
        const size_t off = (size_t)r * (TT * SS) + t * SS + sh + c16 * 8;
        cp16(base + 4096 + sw,  g_WT_hi + off, 16);
        cp16(base + 16384 + sw, g_WT_lo + off, 16);
    }
    cp_commit();
}

__global__ void __launch_bounds__(256) k234_fused(const float* __restrict__ bw,
                                                  const float* __restrict__ uz_ur,
                                                  const float* __restrict__ uh,
                                                  const int* __restrict__ iters, int it_idx) {
    if (it_idx >= *iters) return;
    extern __shared__ char dsm[];
    const int tid = threadIdx.x;
    const int wid = tid >> 5;
    const int lid = tid & 31;
    const int cib = blockIdx.x;      // m-chunk == hB n-chunk
    const int m0 = cib * 32;
    const uint32_t smem = smem_u32(dsm);

    // prefetch U matrices (group 0)
#pragma unroll
    for (int i = 0; i < 8; i++)
        cp16(smem + P2_U + (uint32_t)(tid + 256 * i) * 16,
             (const char*)uz_ur + (size_t)(tid + 256 * i) * 16, 16);
#pragma unroll
    for (int i = 0; i < 4; i++)
        cp16(smem + P2_U + 32768 + (uint32_t)(tid + 256 * i) * 16,
             (const char*)uh + (size_t)(tid + 256 * i) * 16, 16);
    cp_commit();

    const int wm = wid & 1;          // m16
    const int wn = wid >> 1;         // n48

    float acc[6][4];
#pragma unroll
    for (int b = 0; b < 6; b++)
#pragma unroll
        for (int j = 0; j < 4; j++) acc[b][j] = 0.f;

    const int arow = wm * 16 + (lid & 15);
    const uint32_t abyt = (uint32_t)((lid >> 4) << 4);
    const int brow0 = wn * 48 + ((lid >> 4) << 3) + (lid & 7);
    const uint32_t bbyt = (uint32_t)(((lid >> 3) & 1) << 4);

    k234_load_chunk(tid, m0, 0, smem);
    k234_load_chunk(tid, m0, 1, smem);
    k234_load_chunk(tid, m0, 2, smem);

    for (int ci = 0; ci < KCH; ci++) {
        if (ci + 2 < KCH) cp_wait2();
        else if (ci + 1 < KCH) cp_wait1();
        else cp_wait0();
        __syncthreads();

        const uint32_t base = smem + P2_PIPE + (uint32_t)(ci % 3) * P2_STAGE;
#pragma unroll
        for (int kk = 0; kk < 2; kk++) {
            const uint32_t kb = (uint32_t)(kk * 32);
            uint32_t ah[4], al[4], bh[3][4], bl[3][4];
            {
                const int r = arow;
                const uint32_t ad = base + (uint32_t)(r * 64) + ((kb + abyt) ^ (uint32_t)((r & 6) << 3));
                ldsm4(ah[0], ah[1], ah[2], ah[3], ad);
                ldsm4(al[0], al[1], al[2], al[3], ad + 2048);
            }
#pragma unroll
            for (int bp = 0; bp < 3; bp++) {
                const int r = brow0 + bp * 16;
                const uint32_t bd = base + 4096 + (uint32_t)(r * 64) + ((kb + bbyt) ^ (uint32_t)((r & 6) << 3));
                ldsm4(bh[bp][0], bh[bp][1], bh[bp][2], bh[bp][3], bd);
                ldsm4(bl[bp][0], bl[bp][1], bl[bp][2], bl[bp][3], bd + 12288);
            }
#pragma unroll
            for (int b = 0; b < 6; b++) {
                uint32_t bfh[2] = { bh[b >> 1][(b & 1) * 2], bh[b >> 1][(b & 1) * 2 + 1] };
                uint32_t bfl[2] = { bl[b >> 1][(b & 1) * 2], bl[b >> 1][(b & 1) * 2 + 1] };
                mma16816(acc[b], ah, bfh);
                mma16816(acc[b], al, bfh);
                mma16816(acc[b], ah, bfl);
            }
        }
        if (ci + 3 < KCH) k234_load_chunk(tid, m0, ci + 3, smem);
    }
    __syncthreads();   // pipeline region now reusable

    // ---- write acc -> aw_s (smem, pitch 200) ----
    float* aw_s = (float*)(dsm + P2_PIPE);               // [32][200]
    float* shh  = (float*)(dsm + P2_PIPE + 25600);       // [32][65]
    float* srh  = shh + 32 * 65;                         // [32][64]
    float* sz   = srh + 32 * 64;                         // [32][64]
    const float* sUZ = (const float*)(dsm + P2_U);       // [64][128]
    const float* sUH = (const float*)(dsm + P2_U + 32768); // [64][64]

#pragma unroll
    for (int b = 0; b < 6; b++) {
        const int col = wn * 48 + b * 8 + (lid & 3) * 2;
        const int r0 = wm * 16 + (lid >> 2);
        *(float2*)&aw_s[r0 * 200 + col]       = make_float2(acc[b][0], acc[b][1]);
        *(float2*)&aw_s[(r0 + 8) * 200 + col] = make_float2(acc[b][2], acc[b][3]);
    }
    // load h rows into pitched smem
#pragma unroll
    for (int j = 0; j < 8; j++) {
        const int idx = tid + 256 * j;
        const int r = idx >> 6, s = idx & 63;
        shh[r * 65 + s] = g_h[(size_t)(m0 + r) * SS + s];
    }
    __syncthreads();

    const int tx = tid & 15, ty = tid >> 4;
    {   // gates: 2 rows/thread, 8 k each
        const int k0 = tx * 8;
#pragma unroll
        for (int rr = 0; rr < 2; rr++) {
            const int r = ty + rr * 16;
            float accv[8] = {0.f, 0.f, 0.f, 0.f, 0.f, 0.f, 0.f, 0.f};
#pragma unroll 8
            for (int s = 0; s < 64; s++) {
                const float hv = shh[r * 65 + s];
#pragma unroll
                for (int j = 0; j < 8; j++) accv[j] += hv * sUZ[s * 128 + k0 + j];
            }
#pragma unroll
            for (int j = 0; j < 8; j++) {
                const int k = k0 + j;
                const float gt = aw_s[r * 200 + k] + 12.0f * bw[k] + accv[j];
                const float sg = 1.0f / (1.0f + __expf(-gt));
                if (k < 64) sz[r * 64 + k] = sg;
                else        srh[r * 64 + (k - 64)] = sg * shh[r * 65 + (k - 64)];
            }
        }
    }
    __syncthreads();
    {   // candidate + update: 2 rows/thread, 4 k each
        const int k0 = tx * 4;
#pragma unroll
        for (int rr = 0; rr < 2; rr++) {
            const int r = ty + rr * 16;
            const int m = m0 + r;
            float accv[4] = {0.f, 0.f, 0.f, 0.f};
#pragma unroll 8
            for (int s = 0; s < 64; s++) {
                const float rv = srh[r * 64 + s];
#pragma unroll
                for (int j = 0; j < 4; j++) accv[j] += rv * sUH[s * 64 + k0 + j];
            }
#pragma unroll
            for (int j = 0; j < 4; j++) {
                const int k = k0 + j;
                const float hhv = tanhf(aw_s[r * 200 + 128 + k] + 12.0f * bw[128 + k] + accv[j]);
                const float zv = sz[r * 64 + k];
                const float hv = shh[r * 65 + k];
                const float hnew = (1.0f - zv) * hv + zv * hhv;
                g_h[(size_t)m * SS + k] = hnew;
                shh[r * 65 + k] = hnew;
            }
        }
    }
    __syncthreads();
    {   // hB transpose-write for next iteration's k1
        const int pr = tid & 15;
        const int sb = tid >> 4;
#pragma unroll
        for (int j = 0; j < 4; j++) {
            const int s = sb + 16 * j;
            const float v0 = shh[(2 * pr) * 65 + s];
            const float v1 = shh[(2 * pr + 1) * 65 + s];
            const float h0 = __half2float(__float2half_rn(v0));
            const float h1 = __half2float(__float2half_rn(v1));
            const size_t o = ((size_t)cib * SS + s) * 32 + 2 * pr;
            *(uint32_t*)&g_hB_hi[o] = pack_h2(v0, v1);
            *(uint32_t*)&g_hB_lo[o] = pack_h2(v0 - h0, v1 - h1);
        }
    }
}

// ---- copies ----
__global__ void kcopy_in(const float* __restrict__ x) {
    const int i = blockIdx.x * 256 + threadIdx.x;
    if (i < NN * SS) g_h[i] = x[i];
}
__global__ void kcopy_out(float* __restrict__ out) {
    const int i = blockIdx.x * 256 + threadIdx.x;
    if (i < NN * SS) out[i] = g_h[i];
}

extern "C" void kernel_launch(void* const* d_in, const int* in_sizes, int n_in,
                              void* d_out, int out_size) {
    const float* x     = (const float*)d_in[0];
    const float* e     = (const float*)d_in[1];
    const float* ba    = (const float*)d_in[2];
    const float* bw    = (const float*)d_in[3];
    const float* W     = (const float*)d_in[4];
    const float* uz_ur = (const float*)d_in[5];
    const float* uh    = (const float*)d_in[6];
    const int*   iters = (const int*)d_in[7];
    float* out = (float*)d_out;

    cudaFuncSetAttribute(k1_hmma, cudaFuncAttributeMaxDynamicSharedMemorySize, 4 * K1_STAGE);
    cudaFuncSetAttribute(k1_hmma, cudaFuncAttributePreferredSharedMemoryCarveout, 100);
    cudaFuncSetAttribute(k234_fused, cudaFuncAttributeMaxDynamicSharedMemorySize, P2_DSM);
    cudaFuncSetAttribute(k234_fused, cudaFuncAttributePreferredSharedMemoryCarveout, 100);

    const int cpb = (NN * SS + 255) / 256;
    kcopy_in<<<cpb, 256>>>(x);

    dim3 ge(16, NCH, TT);
    esplit<<<ge, 256>>>(e);
    wsplit<<<(K3S * TT * SS + 255) / 256, 256>>>(W);

    const dim3 gh(NN / 32, SS / 32);
    hsplit<<<gh, 256>>>(iters, 0);   // hB for iteration 0; k234 maintains it after

    const dim3 g1((NN + 127) / 128, TT);

    for (int it = 0; it < 10; it++) {
        k1_hmma<<<g1, 256, 4 * K1_STAGE>>>(ba, iters, it);
        k234_fused<<<NCH, 256, P2_DSM>>>(bw, uz_ur, uh, iters, it);
    }

    kcopy_out<<<cpb, 256>>>(out);
}

// round 14
// speedup vs baseline: 1.2832x; 1.2700x over previous
#include <cuda_runtime.h>
#include <cuda_fp16.h>
#include <cstdint>

#define NN 4000
#define SS 64
#define TT 12
#define K3S 192   // 3*SS
#define NCH 125   // 4000 / 32 n-chunks (k1)
#define KCH 24    // 768 / 32 k-chunks (k234)

// ------------------------- device scratch (no allocs) -------------------------
__device__ __align__(16) float g_h[NN * SS];
__device__ __align__(16) __half g_act_hi[(size_t)TT * NN * SS];
__device__ __align__(16) __half g_act_lo[(size_t)TT * NN * SS];
__device__ __align__(16) __half g_eB_hi[(size_t)TT * NCH * NN * 32];
__device__ __align__(16) __half g_eB_lo[(size_t)TT * NCH * NN * 32];
__device__ __align__(16) __half g_hB_hi[NCH * SS * 32];
__device__ __align__(16) __half g_WT_hi[K3S * TT * SS];
__device__ __align__(16) __half g_WT_lo[K3S * TT * SS];

// ------------------------- helpers -------------------------
__device__ __forceinline__ uint32_t smem_u32(const void* p) {
    uint32_t a;
    asm("{ .reg .u64 t; cvta.to.shared.u64 t, %1; cvt.u32.u64 %0, t; }" : "=r"(a) : "l"(p));
    return a;
}
__device__ __forceinline__ void cp16(uint32_t dst, const void* src, int bytes) {
    asm volatile("cp.async.cg.shared.global [%0], [%1], 16, %2;" :: "r"(dst), "l"(src), "r"(bytes));
}
__device__ __forceinline__ void cp_commit() { asm volatile("cp.async.commit_group;"); }
__device__ __forceinline__ void cp_wait2()  { asm volatile("cp.async.wait_group 2;"); }
__device__ __forceinline__ void cp_wait1()  { asm volatile("cp.async.wait_group 1;"); }
__device__ __forceinline__ void cp_wait0()  { asm volatile("cp.async.wait_group 0;"); }

__device__ __forceinline__ void ldsm4(uint32_t& r0, uint32_t& r1, uint32_t& r2, uint32_t& r3,
                                      uint32_t addr) {
    asm volatile("ldmatrix.sync.aligned.m8n8.x4.shared.b16 {%0,%1,%2,%3}, [%4];"
                 : "=r"(r0), "=r"(r1), "=r"(r2), "=r"(r3) : "r"(addr));
}
__device__ __forceinline__ void mma16816(float* c, const uint32_t* a, const uint32_t* b) {
    asm volatile("mma.sync.aligned.m16n8k16.row.col.f32.f16.f16.f32 "
                 "{%0,%1,%2,%3}, {%4,%5,%6,%7}, {%8,%9}, {%0,%1,%2,%3};"
                 : "+f"(c[0]), "+f"(c[1]), "+f"(c[2]), "+f"(c[3])
                 : "r"(a[0]), "r"(a[1]), "r"(a[2]), "r"(a[3]), "r"(b[0]), "r"(b[1]));
}
__device__ __forceinline__ uint32_t sw64(int r, uint32_t c) {
    return (uint32_t)(r * 64) + (c ^ (uint32_t)((r & 6) << 3));
}
__device__ __forceinline__ uint32_t pack_h2(float a, float b) {
    __half2 h = __floats2half2_rn(a, b);
    return *(uint32_t*)&h;
}

#define K1_STAGE 20480   // k1: Ahi 8K | Alo 8K | Bhi 4K
#define P2_STAGE 28672   // k234: A 2K+2K | B 12K+12K

// =====================================================================
// setup: contiguous-read transpose + fp16 split of E -> eB [t][ci][m][32]
// =====================================================================
__global__ void __launch_bounds__(256) esplit(const float* __restrict__ e) {
    __shared__ float tile[256 * 33];
    const int t = blockIdx.z;
    const int ci = blockIdx.y;
    const int n0 = ci * 32;
    const int m0 = blockIdx.x * 256;
    const int tid = threadIdx.x;
    const float* eb = e + (size_t)t * NN * NN;

#pragma unroll
    for (int j = 0; j < 8; j++) {
        const int idx = tid + 256 * j;
        const int r = idx >> 6;
        const int c4 = idx & 63;
        const int m = m0 + c4 * 4;
        float4 v = make_float4(0.f, 0.f, 0.f, 0.f);
        if (m < NN) v = *(const float4*)(eb + (size_t)(n0 + r) * NN + m);
        const int ml = c4 * 4;
        tile[(ml + 0) * 33 + r] = v.x;
        tile[(ml + 1) * 33 + r] = v.y;
        tile[(ml + 2) * 33 + r] = v.z;
        tile[(ml + 3) * 33 + r] = v.w;
    }
    __syncthreads();

    const size_t rowbase = ((size_t)t * NCH + ci) * NN;
    const int px = tid & 15;
    const int my = tid >> 4;
#pragma unroll
    for (int p = 0; p < 16; p++) {
        const int ml = p * 16 + my;
        const int m = m0 + ml;
        if (m < NN) {
            const float v0 = tile[ml * 33 + 2 * px];
            const float v1 = tile[ml * 33 + 2 * px + 1];
            const float h0 = __half2float(__float2half_rn(v0));
            const float h1 = __half2float(__float2half_rn(v1));
            const size_t o = (rowbase + m) * 32 + 2 * px;
            *(uint32_t*)&g_eB_hi[o] = pack_h2(v0, v1);
            *(uint32_t*)&g_eB_lo[o] = pack_h2(v0 - h0, v1 - h1);
        }
    }
}

// one-time: W^T split  WT[n][k] = W[k/64][k%64][n]
__global__ void __launch_bounds__(256) wsplit(const float* __restrict__ W) {
    const int idx = blockIdx.x * 256 + threadIdx.x;
    if (idx >= K3S * TT * SS) return;
    const int n = idx / (TT * SS);
    const int k = idx - n * (TT * SS);
    const float v = W[(size_t)k * K3S + n];
    const __half hi = __float2half_rn(v);
    g_WT_hi[idx] = hi;
    g_WT_lo[idx] = __float2half_rn(v - __half2float(hi));
}

// once before loop: transpose h -> blocked hB_hi [ci][s][32]
__global__ void __launch_bounds__(256) hsplit(const int* __restrict__ iters, int it_idx) {
    if (it_idx >= *iters) return;
    __shared__ float tile[32][33];
    const int n0 = blockIdx.x * 32;
    const int ci = n0 >> 5;
    const int s0 = blockIdx.y * 32;
    const int tx = threadIdx.x & 31;
    const int ty = threadIdx.x >> 5;
#pragma unroll
    for (int i = 0; i < 4; i++) {
        const int n = n0 + ty + i * 8;
        tile[ty + i * 8][tx] = g_h[(size_t)n * SS + s0 + tx];
    }
    __syncthreads();
#pragma unroll
    for (int i = 0; i < 4; i++) {
        const int s = s0 + ty + i * 8;
        g_hB_hi[((size_t)ci * SS + s) * 32 + tx] = __float2half_rn(tile[tx][ty + i * 8]);
    }
}

// =====================================================================
// K1 (HMMA): act[t,m,s] = sum_n e[t,n,m] * h[n,s] + ba[t,s]  -> fp16 hi/lo
// 2-product split: (Ehi+Elo)*Hhi. grid (32 m-tiles, 12 t), block 256.
// 4-stage x 20KB, wait<=2.
// =====================================================================
__device__ __forceinline__ void k1_load_chunk(int tid, int t, int m0, int ci, uint32_t smem) {
    const uint32_t base = smem + (uint32_t)(ci & 3) * K1_STAGE;
    const size_t arow = ((size_t)t * NCH + ci) * NN;
#pragma unroll
    for (int q = 0; q < 2; q++) {
        const int idx = tid + 256 * q;
        const int r = idx >> 2, c16 = idx & 3;
        const int m = m0 + r;
        const int ok = (m < NN) ? 16 : 0;
        const int mc = (m < NN) ? m : (NN - 1);
        const uint32_t sw = sw64(r, (uint32_t)(c16 * 16));
        const size_t off = (arow + mc) * 32 + c16 * 8;
        cp16(base + sw,        g_eB_hi + off, ok);
        cp16(base + 8192 + sw, g_eB_lo + off, ok);
    }
    if (tid < 256) {
        const int r = tid >> 2, c16 = tid & 3;
        const uint32_t sw = sw64(r, (uint32_t)(c16 * 16));
        const size_t off = ((size_t)ci * SS + r) * 32 + c16 * 8;
        cp16(base + 16384 + sw, g_hB_hi + off, 16);
    }
    cp_commit();
}

__global__ void __launch_bounds__(256) k1_hmma(const float* __restrict__ ba,
                                               const int* __restrict__ iters, int it_idx) {
    if (it_idx >= *iters) return;
    extern __shared__ char dsm[];
    const int tid = threadIdx.x;
    const int wid = tid >> 5;
    const int lid = tid & 31;
    const int tt = blockIdx.y;
    const int m0 = blockIdx.x * 128;
    const uint32_t smem = smem_u32(dsm);

    const int wm = wid & 3;
    const int ws = wid >> 2;

    float acc[2][4][4];
#pragma unroll
    for (int a = 0; a < 2; a++)
#pragma unroll
        for (int b = 0; b < 4; b++)
#pragma unroll
            for (int j = 0; j < 4; j++) acc[a][b][j] = 0.f;

    const int arow = wm * 32 + (lid & 15);
    const uint32_t abyt = (uint32_t)((lid >> 4) << 4);
    const int brow0 = ws * 32 + ((lid >> 4) << 3) + (lid & 7);
    const uint32_t bbyt = (uint32_t)(((lid >> 3) & 1) << 4);

    k1_load_chunk(tid, tt, m0, 0, smem);
    k1_load_chunk(tid, tt, m0, 1, smem);
    k1_load_chunk(tid, tt, m0, 2, smem);

    for (int ci = 0; ci < NCH; ci++) {
        if (ci + 2 < NCH) cp_wait2();
        else if (ci + 1 < NCH) cp_wait1();
        else cp_wait0();
        __syncthreads();

        const uint32_t base = smem + (uint32_t)(ci & 3) * K1_STAGE;
#pragma unroll
        for (int kk = 0; kk < 2; kk++) {
            const uint32_t kb = (uint32_t)(kk * 32);
            uint32_t ah[2][4], al[2][4], bh[2][4];
#pragma unroll
            for (int a = 0; a < 2; a++) {
                const int r = arow + a * 16;
                const uint32_t ad = base + (uint32_t)(r * 64) + ((kb + abyt) ^ (uint32_t)((r & 6) << 3));
                ldsm4(ah[a][0], ah[a][1], ah[a][2], ah[a][3], ad);
                ldsm4(al[a][0], al[a][1], al[a][2], al[a][3], ad + 8192);
            }
#pragma unroll
            for (int bp = 0; bp < 2; bp++) {
                const int r = brow0 + bp * 16;
                const uint32_t bd = base + 16384 + (uint32_t)(r * 64) + ((kb + bbyt) ^ (uint32_t)((r & 6) << 3));
                ldsm4(bh[bp][0], bh[bp][1], bh[bp][2], bh[bp][3], bd);
            }
#pragma unroll
            for (int a = 0; a < 2; a++)
#pragma unroll
                for (int b = 0; b < 4; b++) {
                    uint32_t bfh[2] = { bh[b >> 1][(b & 1) * 2], bh[b >> 1][(b & 1) * 2 + 1] };
                    mma16816(acc[a][b], ah[a], bfh);   // Ehi*Hhi
                    mma16816(acc[a][b], al[a], bfh);   // Elo*Hhi
                }
        }
        if (ci + 3 < NCH) k1_load_chunk(tid, tt, m0, ci + 3, smem);
    }

#pragma unroll
    for (int b = 0; b < 4; b++) {
        const int scol = ws * 32 + b * 8 + (lid & 3) * 2;
        const float2 bav = *(const float2*)(ba + tt * SS + scol);
#pragma unroll
        for (int a = 0; a < 2; a++) {
            const int mrow = m0 + wm * 32 + a * 16 + (lid >> 2);
#pragma unroll
            for (int half8 = 0; half8 < 2; half8++) {
                const int mr = mrow + half8 * 8;
                if (mr < NN) {
                    const float ox = acc[a][b][half8 * 2 + 0] + bav.x;
                    const float oy = acc[a][b][half8 * 2 + 1] + bav.y;
                    const float hx = __half2float(__float2half_rn(ox));
                    const float hy = __half2float(__float2half_rn(oy));
                    const size_t o = ((size_t)tt * NN + mr) * SS + scol;
                    *(uint32_t*)&g_act_hi[o] = pack_h2(ox, oy);
                    *(uint32_t*)&g_act_lo[o] = pack_h2(ox - hx, oy - hy);
                }
            }
        }
    }
}

// =====================================================================
// K234 (fused): per 32-row m-chunk (grid 125): aw GEMM (3-product) in smem,
// then GRU + hB_hi transpose-write.
// =====================================================================
#define P2_U    0
#define P2_PIPE 49152
#define P2_DSM  (49152 + 3 * P2_STAGE)   // 135168

__device__ __forceinline__ void k234_load_chunk(int tid, int m0, int ci, uint32_t smem) {
    const uint32_t base = smem + P2_PIPE + (uint32_t)(ci % 3) * P2_STAGE;
    const int t = ci >> 1;
    const int sh = (ci & 1) * 32;
    if (tid < 128) {
        const int r = tid >> 2, c16 = tid & 3;
        const int m = m0 + r;
        const uint32_t sw = sw64(r, (uint32_t)(c16 * 16));
        const size_t off = ((size_t)t * NN + m) * SS + sh + c16 * 8;
        cp16(base + sw,        g_act_hi + off, 16);
        cp16(base + 2048 + sw, g_act_lo + off, 16);
    }
#pragma unroll
    for (int q = 0; q < 3; q++) {
        const int idx = tid + 256 * q;
        const int r = idx >> 2, c16 = idx & 3;
        const uint32_t sw = sw64(r, (uint32_t)(c16 * 16));
        const size_t off = (size_t)r * (TT * SS) + t * SS + sh + c16 * 8;
        cp16(base + 4096 + sw,  g_WT_hi + off, 16);
        cp16(base + 16384 + sw, g_WT_lo + off, 16);
    }
    cp_commit();
}

__global__ void __launch_bounds__(256) k234_fused(const float* __restrict__ bw,
                                                  const float* __restrict__ uz_ur,
                                                  const float* __restrict__ uh,
                                                  const int* __restrict__ iters, int it_idx) {
    if (it_idx >= *iters) return;
    extern __shared__ char dsm[];
    const int tid = threadIdx.x;
    const int wid = tid >> 5;
    const int lid = tid & 31;
    const int cib = blockIdx.x;
    const int m0 = cib * 32;
    const uint32_t smem = smem_u32(dsm);

#pragma unroll
    for (int i = 0; i < 8; i++)
        cp16(smem + P2_U + (uint32_t)(tid + 256 * i) * 16,
             (const char*)uz_ur + (size_t)(tid + 256 * i) * 16, 16);
#pragma unroll
    for (int i = 0; i < 4; i++)
        cp16(smem + P2_U + 32768 + (uint32_t)(tid + 256 * i) * 16,
             (const char*)uh + (size_t)(tid + 256 * i) * 16, 16);
    cp_commit();

    const int wm = wid & 1;
    const int wn = wid >> 1;

    float acc[6][4];
#pragma unroll
    for (int b = 0; b < 6; b++)
#pragma unroll
        for (int j = 0; j < 4; j++) acc[b][j] = 0.f;

    const int arow = wm * 16 + (lid & 15);
    const uint32_t abyt = (uint32_t)((lid >> 4) << 4);
    const int brow0 = wn * 48 + ((lid >> 4) << 3) + (lid & 7);
    const uint32_t bbyt = (uint32_t)(((lid >> 3) & 1) << 4);

    k234_load_chunk(tid, m0, 0, smem);
    k234_load_chunk(tid, m0, 1, smem);
    k234_load_chunk(tid, m0, 2, smem);

    for (int ci = 0; ci < KCH; ci++) {
        if (ci + 2 < KCH) cp_wait2();
        else if (ci + 1 < KCH) cp_wait1();
        else cp_wait0();
        __syncthreads();

        const uint32_t base = smem + P2_PIPE + (uint32_t)(ci % 3) * P2_STAGE;
#pragma unroll
        for (int kk = 0; kk < 2; kk++) {
            const uint32_t kb = (uint32_t)(kk * 32);
            uint32_t ah[4], al[4], bh[3][4], bl[3][4];
            {
                const int r = arow;
                const uint32_t ad = base + (uint32_t)(r * 64) + ((kb + abyt) ^ (uint32_t)((r & 6) << 3));
                ldsm4(ah[0], ah[1], ah[2], ah[3], ad);
                ldsm4(al[0], al[1], al[2], al[3], ad + 2048);
            }
#pragma unroll
            for (int bp = 0; bp < 3; bp++) {
                const int r = brow0 + bp * 16;
                const uint32_t bd = base + 4096 + (uint32_t)(r * 64) + ((kb + bbyt) ^ (uint32_t)((r & 6) << 3));
                ldsm4(bh[bp][0], bh[bp][1], bh[bp][2], bh[bp][3], bd);
                ldsm4(bl[bp][0], bl[bp][1], bl[bp][2], bl[bp][3], bd + 12288);
            }
#pragma unroll
            for (int b = 0; b < 6; b++) {
                uint32_t bfh[2] = { bh[b >> 1][(b & 1) * 2], bh[b >> 1][(b & 1) * 2 + 1] };
                uint32_t bfl[2] = { bl[b >> 1][(b & 1) * 2], bl[b >> 1][(b & 1) * 2 + 1] };
                mma16816(acc[b], ah, bfh);
                mma16816(acc[b], al, bfh);
                mma16816(acc[b], ah, bfl);
            }
        }
        if (ci + 3 < KCH) k234_load_chunk(tid, m0, ci + 3, smem);
    }
    __syncthreads();

    float* aw_s = (float*)(dsm + P2_PIPE);                 // [32][200]
    float* shh  = (float*)(dsm + P2_PIPE + 25600);         // [32][65]
    float* srh  = shh + 32 * 65;                           // [32][64]
    float* sz   = srh + 32 * 64;                           // [32][64]
    const float* sUZ = (const float*)(dsm + P2_U);         // [64][128]
    const float* sUH = (const float*)(dsm + P2_U + 32768); // [64][64]

#pragma unroll
    for (int b = 0; b < 6; b++) {
        const int col = wn * 48 + b * 8 + (lid & 3) * 2;
        const int r0 = wm * 16 + (lid >> 2);
        *(float2*)&aw_s[r0 * 200 + col]       = make_float2(acc[b][0], acc[b][1]);
        *(float2*)&aw_s[(r0 + 8) * 200 + col] = make_float2(acc[b][2], acc[b][3]);
    }
#pragma unroll
    for (int j = 0; j < 8; j++) {
        const int idx = tid + 256 * j;
        const int r = idx >> 6, s = idx & 63;
        shh[r * 65 + s] = g_h[(size_t)(m0 + r) * SS + s];
    }
    __syncthreads();

    const int tx = tid & 15, ty = tid >> 4;
    {
        const int k0 = tx * 8;
#pragma unroll
        for (int rr = 0; rr < 2; rr++) {
            const int r = ty + rr * 16;
            float accv[8] = {0.f, 0.f, 0.f, 0.f, 0.f, 0.f, 0.f, 0.f};
#pragma unroll 8
            for (int s = 0; s < 64; s++) {
                const float hv = shh[r * 65 + s];
#pragma unroll
                for (int j = 0; j < 8; j++) accv[j] += hv * sUZ[s * 128 + k0 + j];
            }
#pragma unroll
            for (int j = 0; j < 8; j++) {
                const int k = k0 + j;
                const float gt = aw_s[r * 200 + k] + 12.0f * bw[k] + accv[j];
                const float sg = 1.0f / (1.0f + __expf(-gt));
                if (k < 64) sz[r * 64 + k] = sg;
                else        srh[r * 64 + (k - 64)] = sg * shh[r * 65 + (k - 64)];
            }
        }
    }
    __syncthreads();
    {
        const int k0 = tx * 4;
#pragma unroll
        for (int rr = 0; rr < 2; rr++) {
            const int r = ty + rr * 16;
            const int m = m0 + r;
            float accv[4] = {0.f, 0.f, 0.f, 0.f};
#pragma unroll 8
            for (int s = 0; s < 64; s++) {
                const float rv = srh[r * 64 + s];
#pragma unroll
                for (int j = 0; j < 4; j++) accv[j] += rv * sUH[s * 64 + k0 + j];
            }
#pragma unroll
            for (int j = 0; j < 4; j++) {
                const int k = k0 + j;
                const float hhv = tanhf(aw_s[r * 200 + 128 + k] + 12.0f * bw[128 + k] + accv[j]);
                const float zv = sz[r * 64 + k];
                const float hv = shh[r * 65 + k];
                const float hnew = (1.0f - zv) * hv + zv * hhv;
                g_h[(size_t)m * SS + k] = hnew;
                shh[r * 65 + k] = hnew;
            }
        }
    }
    __syncthreads();
    {   // hB_hi transpose-write for next iteration's k1
        const int pr = tid & 15;
        const int sb = tid >> 4;
#pragma unroll
        for (int j = 0; j < 4; j++) {
            const int s = sb + 16 * j;
            const float v0 = shh[(2 * pr) * 65 + s];
            const float v1 = shh[(2 * pr + 1) * 65 + s];
            const size_t o = ((size_t)cib * SS + s) * 32 + 2 * pr;
            *(uint32_t*)&g_hB_hi[o] = pack_h2(v0, v1);
        }
    }
}

// ---- copies ----
__global__ void kcopy_in(const float* __restrict__ x) {
    const int i = blockIdx.x * 256 + threadIdx.x;
    if (i < NN * SS) g_h[i] = x[i];
}
__global__ void kcopy_out(float* __restrict__ out) {
    const int i = blockIdx.x * 256 + threadIdx.x;
    if (i < NN * SS) out[i] = g_h[i];
}

extern "C" void kernel_launch(void* const* d_in, const int* in_sizes, int n_in,
                              void* d_out, int out_size) {
    const float* x     = (const float*)d_in[0];
    const float* e     = (const float*)d_in[1];
    const float* ba    = (const float*)d_in[2];
    const float* bw    = (const float*)d_in[3];
    const float* W     = (const float*)d_in[4];
    const float* uz_ur = (const float*)d_in[5];
    const float* uh    = (const float*)d_in[6];
    const int*   iters = (const int*)d_in[7];
    float* out = (float*)d_out;

    cudaFuncSetAttribute(k1_hmma, cudaFuncAttributeMaxDynamicSharedMemorySize, 4 * K1_STAGE);
    cudaFuncSetAttribute(k1_hmma, cudaFuncAttributePreferredSharedMemoryCarveout, 100);
    cudaFuncSetAttribute(k234_fused, cudaFuncAttributeMaxDynamicSharedMemorySize, P2_DSM);
    cudaFuncSetAttribute(k234_fused, cudaFuncAttributePreferredSharedMemoryCarveout, 100);

    const int cpb = (NN * SS + 255) / 256;
    kcopy_in<<<cpb, 256>>>(x);

    dim3 ge(16, NCH, TT);
    esplit<<<ge, 256>>>(e);
    wsplit<<<(K3S * TT * SS + 255) / 256, 256>>>(W);

    const dim3 gh(NN / 32, SS / 32);
    hsplit<<<gh, 256>>>(iters, 0);   // hB for iteration 0; k234 maintains it after

    const dim3 g1((NN + 127) / 128, TT);

    for (int it = 0; it < 10; it++) {
        k1_hmma<<<g1, 256, 4 * K1_STAGE>>>(ba, iters, it);
        k234_fused<<<NCH, 256, P2_DSM>>>(bw, uz_ur, uh, iters, it);
    }

    kcopy_out<<<cpb, 256>>>(out);
}

// round 15
// speedup vs baseline: 1.3066x; 1.0182x over previous
#include <cuda_runtime.h>
#include <cuda_fp16.h>
#include <cstdint>

#define NN 4000
#define SS 64
#define TT 12
#define K3S 192   // 3*SS
#define NCH 125   // 4000 / 32 n-chunks (k1)
#define KCH 24    // 768 / 32 k-chunks (k234)

// ------------------------- device scratch (no allocs) -------------------------
__device__ __align__(16) float g_h[NN * SS];
__device__ __align__(16) __half g_act_hi[(size_t)TT * NN * SS];
__device__ __align__(16) __half g_act_lo[(size_t)TT * NN * SS];
__device__ __align__(16) __half g_eB_hi[(size_t)TT * NCH * NN * 32];
__device__ __align__(16) __half g_eB_lo[(size_t)TT * NCH * NN * 32];
__device__ __align__(16) __half g_hB_hi[NCH * SS * 32];
__device__ __align__(16) __half g_WT_hi[K3S * TT * SS];
__device__ __align__(16) __half g_WT_lo[K3S * TT * SS];

// ------------------------- helpers -------------------------
__device__ __forceinline__ uint32_t smem_u32(const void* p) {
    uint32_t a;
    asm("{ .reg .u64 t; cvta.to.shared.u64 t, %1; cvt.u32.u64 %0, t; }" : "=r"(a) : "l"(p));
    return a;
}
__device__ __forceinline__ void cp16(uint32_t dst, const void* src, int bytes) {
    asm volatile("cp.async.cg.shared.global [%0], [%1], 16, %2;" :: "r"(dst), "l"(src), "r"(bytes));
}
__device__ __forceinline__ void cp_commit() { asm volatile("cp.async.commit_group;"); }
__device__ __forceinline__ void cp_wait2()  { asm volatile("cp.async.wait_group 2;"); }
__device__ __forceinline__ void cp_wait1()  { asm volatile("cp.async.wait_group 1;"); }
__device__ __forceinline__ void cp_wait0()  { asm volatile("cp.async.wait_group 0;"); }

__device__ __forceinline__ void ldsm4(uint32_t& r0, uint32_t& r1, uint32_t& r2, uint32_t& r3,
                                      uint32_t addr) {
    asm volatile("ldmatrix.sync.aligned.m8n8.x4.shared.b16 {%0,%1,%2,%3}, [%4];"
                 : "=r"(r0), "=r"(r1), "=r"(r2), "=r"(r3) : "r"(addr));
}
__device__ __forceinline__ void mma16816(float* c, const uint32_t* a, const uint32_t* b) {
    asm volatile("mma.sync.aligned.m16n8k16.row.col.f32.f16.f16.f32 "
                 "{%0,%1,%2,%3}, {%4,%5,%6,%7}, {%8,%9}, {%0,%1,%2,%3};"
                 : "+f"(c[0]), "+f"(c[1]), "+f"(c[2]), "+f"(c[3])
                 : "r"(a[0]), "r"(a[1]), "r"(a[2]), "r"(a[3]), "r"(b[0]), "r"(b[1]));
}
__device__ __forceinline__ uint32_t sw64(int r, uint32_t c) {
    return (uint32_t)(r * 64) + (c ^ (uint32_t)((r & 6) << 3));
}
__device__ __forceinline__ uint32_t pack_h2(float a, float b) {
    __half2 h = __floats2half2_rn(a, b);
    return *(uint32_t*)&h;
}

#define K1_STAGE 12288   // k1: Ahi 4K | Alo 4K | Bhi 4K
#define P2_STAGE 28672   // k234: A 2K+2K | B 12K+12K

// =====================================================================
// setup: contiguous-read transpose + fp16 split of E -> eB [t][ci][m][32]
// =====================================================================
__global__ void __launch_bounds__(256) esplit(const float* __restrict__ e) {
    __shared__ float tile[256 * 33];
    const int t = blockIdx.z;
    const int ci = blockIdx.y;
    const int n0 = ci * 32;
    const int m0 = blockIdx.x * 256;
    const int tid = threadIdx.x;
    const float* eb = e + (size_t)t * NN * NN;

#pragma unroll
    for (int j = 0; j < 8; j++) {
        const int idx = tid + 256 * j;
        const int r = idx >> 6;
        const int c4 = idx & 63;
        const int m = m0 + c4 * 4;
        float4 v = make_float4(0.f, 0.f, 0.f, 0.f);
        if (m < NN) v = *(const float4*)(eb + (size_t)(n0 + r) * NN + m);
        const int ml = c4 * 4;
        tile[(ml + 0) * 33 + r] = v.x;
        tile[(ml + 1) * 33 + r] = v.y;
        tile[(ml + 2) * 33 + r] = v.z;
        tile[(ml + 3) * 33 + r] = v.w;
    }
    __syncthreads();

    const size_t rowbase = ((size_t)t * NCH + ci) * NN;
    const int px = tid & 15;
    const int my = tid >> 4;
#pragma unroll
    for (int p = 0; p < 16; p++) {
        const int ml = p * 16 + my;
        const int m = m0 + ml;
        if (m < NN) {
            const float v0 = tile[ml * 33 + 2 * px];
            const float v1 = tile[ml * 33 + 2 * px + 1];
            const float h0 = __half2float(__float2half_rn(v0));
            const float h1 = __half2float(__float2half_rn(v1));
            const size_t o = (rowbase + m) * 32 + 2 * px;
            *(uint32_t*)&g_eB_hi[o] = pack_h2(v0, v1);
            *(uint32_t*)&g_eB_lo[o] = pack_h2(v0 - h0, v1 - h1);
        }
    }
}

// one-time: W^T split  WT[n][k] = W[k/64][k%64][n]
__global__ void __launch_bounds__(256) wsplit(const float* __restrict__ W) {
    const int idx = blockIdx.x * 256 + threadIdx.x;
    if (idx >= K3S * TT * SS) return;
    const int n = idx / (TT * SS);
    const int k = idx - n * (TT * SS);
    const float v = W[(size_t)k * K3S + n];
    const __half hi = __float2half_rn(v);
    g_WT_hi[idx] = hi;
    g_WT_lo[idx] = __float2half_rn(v - __half2float(hi));
}

// once before loop: transpose h -> blocked hB_hi [ci][s][32]
__global__ void __launch_bounds__(256) hsplit(const int* __restrict__ iters, int it_idx) {
    if (it_idx >= *iters) return;
    __shared__ float tile[32][33];
    const int n0 = blockIdx.x * 32;
    const int ci = n0 >> 5;
    const int s0 = blockIdx.y * 32;
    const int tx = threadIdx.x & 31;
    const int ty = threadIdx.x >> 5;
#pragma unroll
    for (int i = 0; i < 4; i++) {
        const int n = n0 + ty + i * 8;
        tile[ty + i * 8][tx] = g_h[(size_t)n * SS + s0 + tx];
    }
    __syncthreads();
#pragma unroll
    for (int i = 0; i < 4; i++) {
        const int s = s0 + ty + i * 8;
        g_hB_hi[((size_t)ci * SS + s) * 32 + tx] = __float2half_rn(tile[tx][ty + i * 8]);
    }
}

// =====================================================================
// K1 (HMMA): act[t,m,s] = sum_n e[t,n,m] * h[n,s] + ba[t,s]  -> fp16 hi/lo
// 2-product split. m-tile 64: grid (63, 12) = 756 CTAs, block 256
// (8 warps: 2 m32 x 4 s16). 4-stage x 12KB, wait<=2.
// =====================================================================
__device__ __forceinline__ void k1_load_chunk(int tid, int t, int m0, int ci, uint32_t smem) {
    const uint32_t base = smem + (uint32_t)(ci & 3) * K1_STAGE;
    const size_t arow = ((size_t)t * NCH + ci) * NN;
    {   // A: 64 rows x 4 x 16B (hi + lo)
        const int r = tid >> 2, c16 = tid & 3;
        const int m = m0 + r;
        const int ok = (m < NN) ? 16 : 0;
        const int mc = (m < NN) ? m : (NN - 1);
        const uint32_t sw = sw64(r, (uint32_t)(c16 * 16));
        const size_t off = (arow + mc) * 32 + c16 * 8;
        cp16(base + sw,        g_eB_hi + off, ok);
        cp16(base + 4096 + sw, g_eB_lo + off, ok);
    }
    {   // B: 64 rows x 4 x 16B
        const int r = tid >> 2, c16 = tid & 3;
        const uint32_t sw = sw64(r, (uint32_t)(c16 * 16));
        const size_t off = ((size_t)ci * SS + r) * 32 + c16 * 8;
        cp16(base + 8192 + sw, g_hB_hi + off, 16);
    }
    cp_commit();
}

__global__ void __launch_bounds__(256) k1_hmma(const float* __restrict__ ba,
                                               const int* __restrict__ iters, int it_idx) {
    if (it_idx >= *iters) return;
    extern __shared__ char dsm[];
    const int tid = threadIdx.x;
    const int wid = tid >> 5;
    const int lid = tid & 31;
    const int tt = blockIdx.y;
    const int m0 = blockIdx.x * 64;
    const uint32_t smem = smem_u32(dsm);

    const int wm = wid & 1;      // m32 block
    const int ws = wid >> 1;     // s16 block

    float acc[2][2][4];
#pragma unroll
    for (int a = 0; a < 2; a++)
#pragma unroll
        for (int b = 0; b < 2; b++)
#pragma unroll
            for (int j = 0; j < 4; j++) acc[a][b][j] = 0.f;

    const int arow = wm * 32 + (lid & 15);                      // + a*16
    const uint32_t abyt = (uint32_t)((lid >> 4) << 4);
    const int brow0 = ws * 16 + ((lid >> 4) << 3) + (lid & 7);
    const uint32_t bbyt = (uint32_t)(((lid >> 3) & 1) << 4);

    k1_load_chunk(tid, tt, m0, 0, smem);
    k1_load_chunk(tid, tt, m0, 1, smem);
    k1_load_chunk(tid, tt, m0, 2, smem);

    for (int ci = 0; ci < NCH; ci++) {
        if (ci + 2 < NCH) cp_wait2();
        else if (ci + 1 < NCH) cp_wait1();
        else cp_wait0();
        __syncthreads();

        const uint32_t base = smem + (uint32_t)(ci & 3) * K1_STAGE;
#pragma unroll
        for (int kk = 0; kk < 2; kk++) {
            const uint32_t kb = (uint32_t)(kk * 32);
            uint32_t ah[2][4], al[2][4], bh[4];
#pragma unroll
            for (int a = 0; a < 2; a++) {
                const int r = arow + a * 16;
                const uint32_t ad = base + (uint32_t)(r * 64) + ((kb + abyt) ^ (uint32_t)((r & 6) << 3));
                ldsm4(ah[a][0], ah[a][1], ah[a][2], ah[a][3], ad);
                ldsm4(al[a][0], al[a][1], al[a][2], al[a][3], ad + 4096);
            }
            {
                const int r = brow0;
                const uint32_t bd = base + 8192 + (uint32_t)(r * 64) + ((kb + bbyt) ^ (uint32_t)((r & 6) << 3));
                ldsm4(bh[0], bh[1], bh[2], bh[3], bd);
            }
#pragma unroll
            for (int a = 0; a < 2; a++)
#pragma unroll
                for (int b = 0; b < 2; b++) {
                    uint32_t bfh[2] = { bh[b * 2], bh[b * 2 + 1] };
                    mma16816(acc[a][b], ah[a], bfh);   // Ehi*Hhi
                    mma16816(acc[a][b], al[a], bfh);   // Elo*Hhi
                }
        }
        if (ci + 3 < NCH) k1_load_chunk(tid, tt, m0, ci + 3, smem);
    }

#pragma unroll
    for (int b = 0; b < 2; b++) {
        const int scol = ws * 16 + b * 8 + (lid & 3) * 2;
        const float2 bav = *(const float2*)(ba + tt * SS + scol);
#pragma unroll
        for (int a = 0; a < 2; a++) {
            const int mrow = m0 + wm * 32 + a * 16 + (lid >> 2);
#pragma unroll
            for (int half8 = 0; half8 < 2; half8++) {
                const int mr = mrow + half8 * 8;
                if (mr < NN) {
                    const float ox = acc[a][b][half8 * 2 + 0] + bav.x;
                    const float oy = acc[a][b][half8 * 2 + 1] + bav.y;
                    const float hx = __half2float(__float2half_rn(ox));
                    const float hy = __half2float(__float2half_rn(oy));
                    const size_t o = ((size_t)tt * NN + mr) * SS + scol;
                    *(uint32_t*)&g_act_hi[o] = pack_h2(ox, oy);
                    *(uint32_t*)&g_act_lo[o] = pack_h2(ox - hx, oy - hy);
                }
            }
        }
    }
}

// =====================================================================
// K234 (fused): per 32-row m-chunk (grid 125): aw GEMM (3-product) in smem,
// then GRU + hB_hi transpose-write.
// =====================================================================
#define P2_U    0
#define P2_PIPE 49152
#define P2_DSM  (49152 + 3 * P2_STAGE)   // 135168

__device__ __forceinline__ void k234_load_chunk(int tid, int m0, int ci, uint32_t smem) {
    const uint32_t base = smem + P2_PIPE + (uint32_t)(ci % 3) * P2_STAGE;
    const int t = ci >> 1;
    const int sh = (ci & 1) * 32;
    if (tid < 128) {
        const int r = tid >> 2, c16 = tid & 3;
        const int m = m0 + r;
        const uint32_t sw = sw64(r, (uint32_t)(c16 * 16));
        const size_t off = ((size_t)t * NN + m) * SS + sh + c16 * 8;
        cp16(base + sw,        g_act_hi + off, 16);
        cp16(base + 2048 + sw, g_act_lo + off, 16);
    }
#pragma unroll
    for (int q = 0; q < 3; q++) {
        const int idx = tid + 256 * q;
        const int r = idx >> 2, c16 = idx & 3;
        const uint32_t sw = sw64(r, (uint32_t)(c16 * 16));
        const size_t off = (size_t)r * (TT * SS) + t * SS + sh + c16 * 8;
        cp16(base + 4096 + sw,  g_WT_hi + off, 16);
        cp16(base + 16384 + sw, g_WT_lo + off, 16);
    }
    cp_commit();
}

__global__ void __launch_bounds__(256) k234_fused(const float* __restrict__ bw,
                                                  const float* __restrict__ uz_ur,
                                                  const float* __restrict__ uh,
                                                  const int* __restrict__ iters, int it_idx) {
    if (it_idx >= *iters) return;
    extern __shared__ char dsm[];
    const int tid = threadIdx.x;
    const int wid = tid >> 5;
    const int lid = tid & 31;
    const int cib = blockIdx.x;
    const int m0 = cib * 32;
    const uint32_t smem = smem_u32(dsm);

#pragma unroll
    for (int i = 0; i < 8; i++)
        cp16(smem + P2_U + (uint32_t)(tid + 256 * i) * 16,
             (const char*)uz_ur + (size_t)(tid + 256 * i) * 16, 16);
#pragma unroll
    for (int i = 0; i < 4; i++)
        cp16(smem + P2_U + 32768 + (uint32_t)(tid + 256 * i) * 16,
             (const char*)uh + (size_t)(tid + 256 * i) * 16, 16);
    cp_commit();

    const int wm = wid & 1;
    const int wn = wid >> 1;

    float acc[6][4];
#pragma unroll
    for (int b = 0; b < 6; b++)
#pragma unroll
        for (int j = 0; j < 4; j++) acc[b][j] = 0.f;

    const int arow = wm * 16 + (lid & 15);
    const uint32_t abyt = (uint32_t)((lid >> 4) << 4);
    const int brow0 = wn * 48 + ((lid >> 4) << 3) + (lid & 7);
    const uint32_t bbyt = (uint32_t)(((lid >> 3) & 1) << 4);

    k234_load_chunk(tid, m0, 0, smem);
    k234_load_chunk(tid, m0, 1, smem);
    k234_load_chunk(tid, m0, 2, smem);

    for (int ci = 0; ci < KCH; ci++) {
        if (ci + 2 < KCH) cp_wait2();
        else if (ci + 1 < KCH) cp_wait1();
        else cp_wait0();
        __syncthreads();

        const uint32_t base = smem + P2_PIPE + (uint32_t)(ci % 3) * P2_STAGE;
#pragma unroll
        for (int kk = 0; kk < 2; kk++) {
            const uint32_t kb = (uint32_t)(kk * 32);
            uint32_t ah[4], al[4], bh[3][4], bl[3][4];
            {
                const int r = arow;
                const uint32_t ad = base + (uint32_t)(r * 64) + ((kb + abyt) ^ (uint32_t)((r & 6) << 3));
                ldsm4(ah[0], ah[1], ah[2], ah[3], ad);
                ldsm4(al[0], al[1], al[2], al[3], ad + 2048);
            }
#pragma unroll
            for (int bp = 0; bp < 3; bp++) {
                const int r = brow0 + bp * 16;
                const uint32_t bd = base + 4096 + (uint32_t)(r * 64) + ((kb + bbyt) ^ (uint32_t)((r & 6) << 3));
                ldsm4(bh[bp][0], bh[bp][1], bh[bp][2], bh[bp][3], bd);
                ldsm4(bl[bp][0], bl[bp][1], bl[bp][2], bl[bp][3], bd + 12288);
            }
#pragma unroll
            for (int b = 0; b < 6; b++) {
                uint32_t bfh[2] = { bh[b >> 1][(b & 1) * 2], bh[b >> 1][(b & 1) * 2 + 1] };
                uint32_t bfl[2] = { bl[b >> 1][(b & 1) * 2], bl[b >> 1][(b & 1) * 2 + 1] };
                mma16816(acc[b], ah, bfh);
                mma16816(acc[b], al, bfh);
                mma16816(acc[b], ah, bfl);
            }
        }
        if (ci + 3 < KCH) k234_load_chunk(tid, m0, ci + 3, smem);
    }
    __syncthreads();

    float* aw_s = (float*)(dsm + P2_PIPE);                 // [32][200]
    float* shh  = (float*)(dsm + P2_PIPE + 25600);         // [32][65]
    float* srh  = shh + 32 * 65;                           // [32][64]
    float* sz   = srh + 32 * 64;                           // [32][64]
    const float* sUZ = (const float*)(dsm + P2_U);         // [64][128]
    const float* sUH = (const float*)(dsm + P2_U + 32768); // [64][64]

#pragma unroll
    for (int b = 0; b < 6; b++) {
        const int col = wn * 48 + b * 8 + (lid & 3) * 2;
        const int r0 = wm * 16 + (lid >> 2);
        *(float2*)&aw_s[r0 * 200 + col]       = make_float2(acc[b][0], acc[b][1]);
        *(float2*)&aw_s[(r0 + 8) * 200 + col] = make_float2(acc[b][2], acc[b][3]);
    }
#pragma unroll
    for (int j = 0; j < 8; j++) {
        const int idx = tid + 256 * j;
        const int r = idx >> 6, s = idx & 63;
        shh[r * 65 + s] = g_h[(size_t)(m0 + r) * SS + s];
    }
    __syncthreads();

    const int tx = tid & 15, ty = tid >> 4;
    {
        const int k0 = tx * 8;
#pragma unroll
        for (int rr = 0; rr < 2; rr++) {
            const int r = ty + rr * 16;
            float accv[8] = {0.f, 0.f, 0.f, 0.f, 0.f, 0.f, 0.f, 0.f};
#pragma unroll 8
            for (int s = 0; s < 64; s++) {
                const float hv = shh[r * 65 + s];
#pragma unroll
                for (int j = 0; j < 8; j++) accv[j] += hv * sUZ[s * 128 + k0 + j];
            }
#pragma unroll
            for (int j = 0; j < 8; j++) {
                const int k = k0 + j;
                const float gt = aw_s[r * 200 + k] + 12.0f * bw[k] + accv[j];
                const float sg = 1.0f / (1.0f + __expf(-gt));
                if (k < 64) sz[r * 64 + k] = sg;
                else        srh[r * 64 + (k - 64)] = sg * shh[r * 65 + (k - 64)];
            }
        }
    }
    __syncthreads();
    {
        const int k0 = tx * 4;
#pragma unroll
        for (int rr = 0; rr < 2; rr++) {
            const int r = ty + rr * 16;
            const int m = m0 + r;
            float accv[4] = {0.f, 0.f, 0.f, 0.f};
#pragma unroll 8
            for (int s = 0; s < 64; s++) {
                const float rv = srh[r * 64 + s];
#pragma unroll
                for (int j = 0; j < 4; j++) accv[j] += rv * sUH[s * 64 + k0 + j];
            }
#pragma unroll
            for (int j = 0; j < 4; j++) {
                const int k = k0 + j;
                const float hhv = tanhf(aw_s[r * 200 + 128 + k] + 12.0f * bw[128 + k] + accv[j]);
                const float zv = sz[r * 64 + k];
                const float hv = shh[r * 65 + k];
                const float hnew = (1.0f - zv) * hv + zv * hhv;
                g_h[(size_t)m * SS + k] = hnew;
                shh[r * 65 + k] = hnew;
            }
        }
    }
    __syncthreads();
    {   // hB_hi transpose-write for next iteration's k1
        const int pr = tid & 15;
        const int sb = tid >> 4;
#pragma unroll
        for (int j = 0; j < 4; j++) {
            const int s = sb + 16 * j;
            const float v0 = shh[(2 * pr) * 65 + s];
            const float v1 = shh[(2 * pr + 1) * 65 + s];
            const size_t o = ((size_t)cib * SS + s) * 32 + 2 * pr;
            *(uint32_t*)&g_hB_hi[o] = pack_h2(v0, v1);
        }
    }
}

// ---- copies ----
__global__ void kcopy_in(const float* __restrict__ x) {
    const int i = blockIdx.x * 256 + threadIdx.x;
    if (i < NN * SS) g_h[i] = x[i];
}
__global__ void kcopy_out(float* __restrict__ out) {
    const int i = blockIdx.x * 256 + threadIdx.x;
    if (i < NN * SS) out[i] = g_h[i];
}

extern "C" void kernel_launch(void* const* d_in, const int* in_sizes, int n_in,
                              void* d_out, int out_size) {
    const float* x     = (const float*)d_in[0];
    const float* e     = (const float*)d_in[1];
    const float* ba    = (const float*)d_in[2];
    const float* bw    = (const float*)d_in[3];
    const float* W     = (const float*)d_in[4];
    const float* uz_ur = (const float*)d_in[5];
    const float* uh    = (const float*)d_in[6];
    const int*   iters = (const int*)d_in[7];
    float* out = (float*)d_out;

    cudaFuncSetAttribute(k1_hmma, cudaFuncAttributeMaxDynamicSharedMemorySize, 4 * K1_STAGE);
    cudaFuncSetAttribute(k1_hmma, cudaFuncAttributePreferredSharedMemoryCarveout, 100);
    cudaFuncSetAttribute(k234_fused, cudaFuncAttributeMaxDynamicSharedMemorySize, P2_DSM);
    cudaFuncSetAttribute(k234_fused, cudaFuncAttributePreferredSharedMemoryCarveout, 100);

    const int cpb = (NN * SS + 255) / 256;
    kcopy_in<<<cpb, 256>>>(x);

    dim3 ge(16, NCH, TT);
    esplit<<<ge, 256>>>(e);
    wsplit<<<(K3S * TT * SS + 255) / 256, 256>>>(W);

    const dim3 gh(NN / 32, SS / 32);
    hsplit<<<gh, 256>>>(iters, 0);   // hB for iteration 0; k234 maintains it after

    const dim3 g1((NN + 63) / 64, TT);

    for (int it = 0; it < 10; it++) {
        k1_hmma<<<g1, 256, 4 * K1_STAGE>>>(ba, iters, it);
        k234_fused<<<NCH, 256, P2_DSM>>>(bw, uz_ur, uh, iters, it);
    }

    kcopy_out<<<cpb, 256>>>(out);
}